// round 12
// baseline (speedup 1.0000x reference)
#include <cuda_runtime.h>
#include <cuda_bf16.h>
#include <mma.h>
#include <math.h>

// Problem-fixed capacities
#define NMAX 50000
#define NPAD 50048
#define EMAX 800000
#define SCAN_BLK 256
#define SCAN_GRID ((NMAX + SCAN_BLK - 1) / SCAN_BLK)   // 196

// ---------------- scratch (no allocation allowed) ----------------
__device__ int   g_is64;
__device__ int   g_deg[NMAX];
__device__ int   g_cursor[NMAX];
__device__ float g_dinv[NMAX];
__device__ int   g_rowptr[NMAX + 1];
__device__ int   g_col[EMAX];
__device__ float g_w[EMAX];
__device__ int   g_bsum[SCAN_GRID];
__device__ int   g_boff[SCAN_GRID];
__device__ __align__(256) float g_bufA[NPAD * 128];   // GEMM1 out (f32)
__device__ __align__(256) float g_bufB[NPAD * 64];    // GEMM2 out (f32)
__device__ __align__(256) __nv_bfloat16 g_xh[NPAD * 128];
__device__ __align__(256) __nv_bfloat16 g_xl[NPAD * 128];
__device__ __align__(256) __nv_bfloat16 g_h1h[NPAD * 128];
__device__ __align__(256) __nv_bfloat16 g_h1l[NPAD * 128];
__device__ __align__(256) __nv_bfloat16 g_W1h[128 * 128];
__device__ __align__(256) __nv_bfloat16 g_W1l[128 * 128];
__device__ __align__(256) __nv_bfloat16 g_W2h[128 * 64];
__device__ __align__(256) __nv_bfloat16 g_W2l[128 * 64];

// Edge index accessor: handles int32 (JAX x64-disabled) and int64 layouts.
__device__ __forceinline__ int edge_at(const void* ei, long idx) {
    if (g_is64) {
        return (int)((const long long*)ei)[idx];
    }
    return ((const int*)ei)[idx];
}

// ---------------- dtype detection ----------------
__global__ void k_detect(const void* ei, int e) {
    const long long* p = (const long long*)ei;
    int m = e < 2048 ? e : 2048;
    int ok = 1;
    for (int i = threadIdx.x; i < m; i += blockDim.x) {
        long long v = p[i];
        if (v < 0 || v >= NMAX) {
            ok = 0;
        }
    }
    int all = __syncthreads_and(ok);
    if (threadIdx.x == 0) {
        g_is64 = all;
    }
}

// ---------------- degree count ----------------
__global__ void k_count(const void* __restrict__ ei, int e) {
    int i4 = (blockIdx.x * blockDim.x + threadIdx.x) * 4;
    if (i4 >= e) {
        return;
    }
    if (!g_is64 && (e & 3) == 0) {
        const int4* p = (const int4*)((const int*)ei + e);
        int4 d = p[i4 >> 2];
        if (d.x >= 0 && d.x < NMAX) { atomicAdd(&g_deg[d.x], 1); }
        if (d.y >= 0 && d.y < NMAX) { atomicAdd(&g_deg[d.y], 1); }
        if (d.z >= 0 && d.z < NMAX) { atomicAdd(&g_deg[d.z], 1); }
        if (d.w >= 0 && d.w < NMAX) { atomicAdd(&g_deg[d.w], 1); }
    } else {
        int lim = (i4 + 4 < e) ? i4 + 4 : e;
        for (int i = i4; i < lim; i++) {
            int d = edge_at(ei, (long)e + i);
            if (d >= 0 && d < NMAX) { atomicAdd(&g_deg[d], 1); }
        }
    }
}

// ---------------- 3-phase parallel scan ----------------
__global__ void k_scan1(int n) {
    __shared__ int wsum[8];
    int blk = blockIdx.x;
    int tid = threadIdx.x;
    int i = blk * SCAN_BLK + tid;
    int lane = tid & 31;
    int wid = tid >> 5;
    int v = (i < n) ? g_deg[i] : 0;
    if (i < n) {
        g_dinv[i] = rsqrtf((float)(v + 1));
    }
    int incl = v;
    #pragma unroll
    for (int off = 1; off < 32; off <<= 1) {
        int t = __shfl_up_sync(0xffffffffu, incl, off);
        if (lane >= off) { incl += t; }
    }
    if (lane == 31) { wsum[wid] = incl; }
    __syncthreads();
    if (wid == 0 && lane < 8) {
        int ws = wsum[lane];
        int wincl = ws;
        #pragma unroll
        for (int off = 1; off < 8; off <<= 1) {
            int t = __shfl_up_sync(0xffu, wincl, off);
            if (lane >= off) { wincl += t; }
        }
        wsum[lane] = wincl - ws;
        if (lane == 7) { g_bsum[blk] = wincl; }
    }
    __syncthreads();
    if (i < n) {
        g_rowptr[i] = wsum[wid] + incl - v;
    }
}

__global__ void k_scan2(int nblk) {
    __shared__ int wsum[8];
    int tid = threadIdx.x;
    int lane = tid & 31;
    int wid = tid >> 5;
    int v = (tid < nblk) ? g_bsum[tid] : 0;
    int incl = v;
    #pragma unroll
    for (int off = 1; off < 32; off <<= 1) {
        int t = __shfl_up_sync(0xffffffffu, incl, off);
        if (lane >= off) { incl += t; }
    }
    if (lane == 31) { wsum[wid] = incl; }
    __syncthreads();
    if (wid == 0 && lane < 8) {
        int ws = wsum[lane];
        int wincl = ws;
        #pragma unroll
        for (int off = 1; off < 8; off <<= 1) {
            int t = __shfl_up_sync(0xffu, wincl, off);
            if (lane >= off) { wincl += t; }
        }
        wsum[lane] = wincl - ws;
    }
    __syncthreads();
    if (tid < nblk) {
        g_boff[tid] = wsum[wid] + incl - v;
    }
}

__global__ void k_scan3(int n, int e_total) {
    int i = blockIdx.x * blockDim.x + threadIdx.x;
    if (i < n) {
        int r = g_rowptr[i] + g_boff[blockIdx.x];
        g_rowptr[i] = r;
        g_cursor[i] = r;
    }
    if (i == 0) {
        g_rowptr[n] = e_total;
    }
}

// ---------------- CSR fill ----------------
__global__ void k_fill(const void* __restrict__ ei, int e) {
    int i4 = (blockIdx.x * blockDim.x + threadIdx.x) * 4;
    if (i4 >= e) {
        return;
    }
    if (!g_is64 && (e & 3) == 0) {
        const int4* ps = (const int4*)(const int*)ei;
        const int4* pd = (const int4*)((const int*)ei + e);
        int4 s = ps[i4 >> 2];
        int4 d = pd[i4 >> 2];
        int sa[4];
        int da[4];
        sa[0] = s.x; sa[1] = s.y; sa[2] = s.z; sa[3] = s.w;
        da[0] = d.x; da[1] = d.y; da[2] = d.z; da[3] = d.w;
        #pragma unroll
        for (int j = 0; j < 4; j++) {
            int ss = sa[j];
            int dd = da[j];
            if (ss >= 0 && ss < NMAX && dd >= 0 && dd < NMAX) {
                int pos = atomicAdd(&g_cursor[dd], 1);
                if (pos >= 0 && pos < EMAX) {
                    g_col[pos] = ss;
                    g_w[pos] = g_dinv[ss];
                }
            }
        }
    } else {
        int lim = (i4 + 4 < e) ? i4 + 4 : e;
        for (int i = i4; i < lim; i++) {
            int s = edge_at(ei, i);
            int d = edge_at(ei, (long)e + i);
            if (s >= 0 && s < NMAX && d >= 0 && d < NMAX) {
                int pos = atomicAdd(&g_cursor[d], 1);
                if (pos >= 0 && pos < EMAX) {
                    g_col[pos] = s;
                    g_w[pos] = g_dinv[s];
                }
            }
        }
    }
}

// ---------------- f32 -> bf16 hi/lo split ----------------
__global__ void k_cvt(const float4* __restrict__ src,
                      __nv_bfloat162* __restrict__ hi,
                      __nv_bfloat162* __restrict__ lo, int n4) {
    int i = blockIdx.x * blockDim.x + threadIdx.x;
    if (i >= n4) {
        return;
    }
    float4 v = src[i];
    __nv_bfloat16 h0 = __float2bfloat16(v.x);
    __nv_bfloat16 h1 = __float2bfloat16(v.y);
    __nv_bfloat16 h2 = __float2bfloat16(v.z);
    __nv_bfloat16 h3 = __float2bfloat16(v.w);
    __nv_bfloat16 l0 = __float2bfloat16(v.x - __bfloat162float(h0));
    __nv_bfloat16 l1 = __float2bfloat16(v.y - __bfloat162float(h1));
    __nv_bfloat16 l2 = __float2bfloat16(v.z - __bfloat162float(h2));
    __nv_bfloat16 l3 = __float2bfloat16(v.w - __bfloat162float(h3));
    hi[2 * i]     = __halves2bfloat162(h0, h1);
    hi[2 * i + 1] = __halves2bfloat162(h2, h3);
    lo[2 * i]     = __halves2bfloat162(l0, l1);
    lo[2 * i + 1] = __halves2bfloat162(l2, l3);
}

__global__ void k_cvt_w(const float* __restrict__ W1, const float* __restrict__ W2) {
    int i = blockIdx.x * blockDim.x + threadIdx.x;
    if (i < 128 * 128) {
        float v = W1[i];
        __nv_bfloat16 h = __float2bfloat16(v);
        g_W1h[i] = h;
        g_W1l[i] = __float2bfloat16(v - __bfloat162float(h));
    } else if (i < 128 * 128 + 128 * 64) {
        int j = i - 128 * 128;
        float v = W2[j];
        __nv_bfloat16 h = __float2bfloat16(v);
        g_W2h[j] = h;
        g_W2l[j] = __float2bfloat16(v - __bfloat162float(h));
    }
}

// ---------------- wmma bf16x3 GEMM: C[.,ND] = A[.,128] @ B[128,ND] ----------------
// C = Ah@Bh + Ah@Bl + Al@Bh, fp32 accumulate. Warp does 32x32; CTA 8 warps (4m x 2n).
// Grid: (rows/128, ND/64). Buffers padded to NPAD rows -> no bounds checks.
template<int ND>
__global__ void __launch_bounds__(256) k_gemm_wmma(
    const __nv_bfloat16* __restrict__ Ahp, const __nv_bfloat16* __restrict__ Alp,
    const __nv_bfloat16* __restrict__ Bhp, const __nv_bfloat16* __restrict__ Blp,
    float* __restrict__ C)
{
    using namespace nvcuda;
    const int KD = 128;
    int wid = threadIdx.x >> 5;
    int row0 = blockIdx.x * 128 + (wid & 3) * 32;
    int col0 = blockIdx.y * 64 + (wid >> 2) * 32;

    wmma::fragment<wmma::accumulator, 16, 16, 16, float> c[2][2];
    #pragma unroll
    for (int i = 0; i < 2; i++) {
        #pragma unroll
        for (int j = 0; j < 2; j++) {
            wmma::fill_fragment(c[i][j], 0.0f);
        }
    }

    for (int k = 0; k < KD; k += 16) {
        wmma::fragment<wmma::matrix_a, 16, 16, 16, __nv_bfloat16, wmma::row_major> ah[2];
        wmma::fragment<wmma::matrix_a, 16, 16, 16, __nv_bfloat16, wmma::row_major> al[2];
        wmma::fragment<wmma::matrix_b, 16, 16, 16, __nv_bfloat16, wmma::row_major> bh[2];
        wmma::fragment<wmma::matrix_b, 16, 16, 16, __nv_bfloat16, wmma::row_major> bl[2];
        #pragma unroll
        for (int i = 0; i < 2; i++) {
            wmma::load_matrix_sync(ah[i], Ahp + (long)(row0 + 16 * i) * KD + k, KD);
            wmma::load_matrix_sync(al[i], Alp + (long)(row0 + 16 * i) * KD + k, KD);
        }
        #pragma unroll
        for (int j = 0; j < 2; j++) {
            wmma::load_matrix_sync(bh[j], Bhp + (long)k * ND + col0 + 16 * j, ND);
            wmma::load_matrix_sync(bl[j], Blp + (long)k * ND + col0 + 16 * j, ND);
        }
        #pragma unroll
        for (int i = 0; i < 2; i++) {
            #pragma unroll
            for (int j = 0; j < 2; j++) {
                wmma::mma_sync(c[i][j], ah[i], bh[j], c[i][j]);
                wmma::mma_sync(c[i][j], ah[i], bl[j], c[i][j]);
                wmma::mma_sync(c[i][j], al[i], bh[j], c[i][j]);
            }
        }
    }

    #pragma unroll
    for (int i = 0; i < 2; i++) {
        #pragma unroll
        for (int j = 0; j < 2; j++) {
            wmma::store_matrix_sync(C + (long)(row0 + 16 * i) * ND + col0 + 16 * j,
                                    c[i][j], ND, wmma::mem_row_major);
        }
    }
}

// ---------------- layer-1 aggregation (F=128) -> writes h1 as bf16 hi/lo ----------------
// out = tanh(dinv_d * (sum w_p*H[s] + dinv_d*H[d]) + b)
__global__ void __launch_bounds__(256) k_agg128(const float* __restrict__ h,
                                                const float* __restrict__ bias,
                                                int n) {
    int node = blockIdx.x * 8 + (threadIdx.x >> 5);
    if (node >= n) {
        return;
    }
    int lane = threadIdx.x & 31;
    const float4* hv = (const float4*)h;
    float di = g_dinv[node];
    float4 a = __ldg(&hv[(long)node * 32 + lane]);
    float4 acc;
    acc.x = di * a.x;
    acc.y = di * a.y;
    acc.z = di * a.z;
    acc.w = di * a.w;
    int beg = g_rowptr[node];
    int end = g_rowptr[node + 1];
    #pragma unroll 4
    for (int p = beg; p < end; p++) {
        int s = g_col[p];
        float ws = g_w[p];
        float4 v = __ldg(&hv[(long)s * 32 + lane]);
        acc.x += ws * v.x;
        acc.y += ws * v.y;
        acc.z += ws * v.z;
        acc.w += ws * v.w;
    }
    float4 b = __ldg(&((const float4*)bias)[lane]);
    float rx = tanhf(di * acc.x + b.x);
    float ry = tanhf(di * acc.y + b.y);
    float rz = tanhf(di * acc.z + b.z);
    float rw = tanhf(di * acc.w + b.w);
    __nv_bfloat16 h0 = __float2bfloat16(rx);
    __nv_bfloat16 h1 = __float2bfloat16(ry);
    __nv_bfloat16 h2 = __float2bfloat16(rz);
    __nv_bfloat16 h3 = __float2bfloat16(rw);
    __nv_bfloat16 l0 = __float2bfloat16(rx - __bfloat162float(h0));
    __nv_bfloat16 l1 = __float2bfloat16(ry - __bfloat162float(h1));
    __nv_bfloat16 l2 = __float2bfloat16(rz - __bfloat162float(h2));
    __nv_bfloat16 l3 = __float2bfloat16(rw - __bfloat162float(h3));
    __nv_bfloat162* hh = (__nv_bfloat162*)g_h1h;
    __nv_bfloat162* hl = (__nv_bfloat162*)g_h1l;
    long idx = (long)node * 64 + 2 * lane;
    hh[idx]     = __halves2bfloat162(h0, h1);
    hh[idx + 1] = __halves2bfloat162(h2, h3);
    hl[idx]     = __halves2bfloat162(l0, l1);
    hl[idx + 1] = __halves2bfloat162(l2, l3);
}

// ---------------- fused agg(F=64, weighted) + MLP head ----------------
// h2 = tanh(dinv_d*(sum w_p*H2[s] + dinv_d*H2[d]) + b2); out = tanh(h2@Wf1+bf1)@Wf2+bf2
__global__ void __launch_bounds__(256) k_agg64_mlp(const float* __restrict__ h,
                                                   const float* __restrict__ b2,
                                                   const float* __restrict__ Wf1,
                                                   const float* __restrict__ bf1,
                                                   const float* __restrict__ Wf2,
                                                   const float* __restrict__ bf2,
                                                   float* __restrict__ out, int n) {
    __shared__ float sW[64 * 32];
    __shared__ float sb1[32];
    __shared__ float sW2[32];
    __shared__ float sb2;
    __shared__ float stage[8][64];
    for (int i = threadIdx.x; i < 64 * 32; i += blockDim.x) {
        sW[i] = Wf1[i];
    }
    if (threadIdx.x < 32) {
        sb1[threadIdx.x] = bf1[threadIdx.x];
        sW2[threadIdx.x] = Wf2[threadIdx.x];
    }
    if (threadIdx.x == 0) {
        sb2 = bf2[0];
    }
    __syncthreads();

    int w = threadIdx.x >> 5;
    int node = blockIdx.x * 8 + w;
    if (node >= n) {
        return;
    }
    int lane = threadIdx.x & 31;

    const float2* hv = (const float2*)h;
    float di = g_dinv[node];
    float2 a = __ldg(&hv[(long)node * 32 + lane]);
    float2 acc;
    acc.x = di * a.x;
    acc.y = di * a.y;
    int beg = g_rowptr[node];
    int end = g_rowptr[node + 1];
    #pragma unroll 4
    for (int p = beg; p < end; p++) {
        int s = g_col[p];
        float ws = g_w[p];
        float2 v = __ldg(&hv[(long)s * 32 + lane]);
        acc.x += ws * v.x;
        acc.y += ws * v.y;
    }
    float2 bb = __ldg(&((const float2*)b2)[lane]);
    stage[w][2 * lane]     = tanhf(di * acc.x + bb.x);
    stage[w][2 * lane + 1] = tanhf(di * acc.y + bb.y);
    __syncwarp();

    float a1 = sb1[lane];
    #pragma unroll
    for (int j = 0; j < 64; j++) {
        a1 += stage[w][j] * sW[j * 32 + lane];
    }
    float t = tanhf(a1);
    float y = t * sW2[lane];
    #pragma unroll
    for (int off = 16; off; off >>= 1) {
        y += __shfl_down_sync(0xffffffffu, y, off);
    }
    if (lane == 0) {
        out[node] = y + sb2;
    }
}

// ---------------- launch ----------------
extern "C" void kernel_launch(void* const* d_in, const int* in_sizes, int n_in,
                              void* d_out, int out_size) {
    const float* x   = (const float*)d_in[0];
    const void*  ei  = d_in[1];
    const float* W1  = (const float*)d_in[2];
    const float* b1  = (const float*)d_in[3];
    const float* W2  = (const float*)d_in[4];
    const float* b2  = (const float*)d_in[5];
    const float* Wf1 = (const float*)d_in[6];
    const float* bf1 = (const float*)d_in[7];
    const float* Wf2 = (const float*)d_in[8];
    const float* bf2 = (const float*)d_in[9];
    float* out = (float*)d_out;

    int n = in_sizes[0] / 128;   // 50000
    int e = in_sizes[1] / 2;     // 800000

    float* bufA = 0;
    float* bufB = 0;
    int* degp = 0;
    void* xh = 0;
    void* xl = 0;
    void* h1h = 0;
    void* h1l = 0;
    void* w1h = 0;
    void* w1l = 0;
    void* w2h = 0;
    void* w2l = 0;
    cudaGetSymbolAddress((void**)&bufA, g_bufA);
    cudaGetSymbolAddress((void**)&bufB, g_bufB);
    cudaGetSymbolAddress((void**)&degp, g_deg);
    cudaGetSymbolAddress(&xh, g_xh);
    cudaGetSymbolAddress(&xl, g_xl);
    cudaGetSymbolAddress(&h1h, g_h1h);
    cudaGetSymbolAddress(&h1l, g_h1l);
    cudaGetSymbolAddress(&w1h, g_W1h);
    cudaGetSymbolAddress(&w1l, g_W1l);
    cudaGetSymbolAddress(&w2h, g_W2h);
    cudaGetSymbolAddress(&w2l, g_W2l);

    static cudaStream_t sB = 0;
    static cudaEvent_t evFork = 0;
    static cudaEvent_t evJoin = 0;
    if (sB == 0) {
        cudaStreamCreateWithFlags(&sB, cudaStreamNonBlocking);
        cudaEventCreateWithFlags(&evFork, cudaEventDisableTiming);
        cudaEventCreateWithFlags(&evJoin, cudaEventDisableTiming);
    }

    int ge4 = (e + 1023) / 1024;
    int gw  = (n + 7) / 8;
    int gm  = (n + 127) / 128;   // 391, NPAD covers gm*128 rows

    // Fork: CSR build on side stream (fully independent of GEMM path)
    cudaEventRecord(evFork, 0);
    cudaStreamWaitEvent(sB, evFork, 0);

    k_detect<<<1, 1024, 0, sB>>>(ei, e);
    cudaMemsetAsync(degp, 0, (size_t)n * sizeof(int), sB);
    k_count<<<ge4, 256, 0, sB>>>(ei, e);
    k_scan1<<<SCAN_GRID, SCAN_BLK, 0, sB>>>(n);
    k_scan2<<<1, 256, 0, sB>>>(SCAN_GRID);
    k_scan3<<<SCAN_GRID, SCAN_BLK, 0, sB>>>(n, e);
    k_fill<<<ge4, 256, 0, sB>>>(ei, e);
    cudaEventRecord(evJoin, sB);

    // Main stream: conversions + GEMM1 (graph-independent)
    int n4 = n * 128 / 4;
    k_cvt<<<(n4 + 255) / 256, 256>>>((const float4*)x, (__nv_bfloat162*)xh,
                                     (__nv_bfloat162*)xl, n4);
    k_cvt_w<<<(128 * 128 + 128 * 64 + 255) / 256, 256>>>(W1, W2);
    {
        dim3 grid(gm, 2);
        k_gemm_wmma<128><<<grid, 256>>>((const __nv_bfloat16*)xh, (const __nv_bfloat16*)xl,
                                        (const __nv_bfloat16*)w1h, (const __nv_bfloat16*)w1l,
                                        bufA);
    }

    // Join: aggregation needs CSR + dinv + w
    cudaStreamWaitEvent(0, evJoin, 0);
    k_agg128<<<gw, 256>>>(bufA, b1, n);

    // Layer 2: wmma bf16x3 GEMM + fused weighted agg64 + MLP head
    {
        dim3 grid(gm, 1);
        k_gemm_wmma<64><<<grid, 256>>>((const __nv_bfloat16*)h1h, (const __nv_bfloat16*)h1l,
                                       (const __nv_bfloat16*)w2h, (const __nv_bfloat16*)w2l,
                                       bufB);
    }
    k_agg64_mlp<<<gw, 256>>>(bufB, b2, Wf1, bf1, Wf2, bf2, out, n);
}

// round 14
// speedup vs baseline: 1.2183x; 1.2183x over previous
#include <cuda_runtime.h>
#include <cuda_bf16.h>
#include <mma.h>
#include <math.h>

// Problem-fixed capacities
#define NMAX 50000
#define NPAD 50048
#define EMAX 800000
#define SCAN_BLK 256
#define SCAN_GRID ((NMAX + SCAN_BLK - 1) / SCAN_BLK)   // 196

// ---------------- scratch (no allocation allowed) ----------------
__device__ int   g_is64;
__device__ int   g_deg[NMAX];
__device__ int   g_cursor[NMAX];
__device__ float g_dinv[NMAX];
__device__ int   g_rowptr[NMAX + 1];
__device__ int   g_col[EMAX];
__device__ float g_w[EMAX];
__device__ int   g_bsum[SCAN_GRID];
__device__ int   g_boff[SCAN_GRID];
__device__ __align__(256) float g_bufA[NPAD * 128];   // GEMM1 out (f32)
__device__ __align__(256) float g_bufB[NPAD * 64];    // GEMM2 out (f32)
__device__ __align__(256) __nv_bfloat16 g_xh[NPAD * 128];
__device__ __align__(256) __nv_bfloat16 g_xl[NPAD * 128];
__device__ __align__(256) __nv_bfloat16 g_h1h[NPAD * 128];
__device__ __align__(256) __nv_bfloat16 g_h1l[NPAD * 128];
__device__ __align__(256) __nv_bfloat16 g_W1h[128 * 128];
__device__ __align__(256) __nv_bfloat16 g_W1l[128 * 128];
__device__ __align__(256) __nv_bfloat16 g_W2h[128 * 64];
__device__ __align__(256) __nv_bfloat16 g_W2l[128 * 64];

// Edge index accessor: handles int32 (JAX x64-disabled) and int64 layouts.
__device__ __forceinline__ int edge_at(const void* ei, long idx) {
    if (g_is64) {
        return (int)((const long long*)ei)[idx];
    }
    return ((const int*)ei)[idx];
}

// ---------------- dtype detection ----------------
__global__ void k_detect(const void* ei, int e) {
    const long long* p = (const long long*)ei;
    int m = e < 2048 ? e : 2048;
    int ok = 1;
    for (int i = threadIdx.x; i < m; i += blockDim.x) {
        long long v = p[i];
        if (v < 0 || v >= NMAX) {
            ok = 0;
        }
    }
    int all = __syncthreads_and(ok);
    if (threadIdx.x == 0) {
        g_is64 = all;
    }
}

// ---------------- degree count ----------------
__global__ void k_count(const void* __restrict__ ei, int e) {
    int i4 = (blockIdx.x * blockDim.x + threadIdx.x) * 4;
    if (i4 >= e) {
        return;
    }
    if (!g_is64 && (e & 3) == 0) {
        const int4* p = (const int4*)((const int*)ei + e);
        int4 d = p[i4 >> 2];
        if (d.x >= 0 && d.x < NMAX) { atomicAdd(&g_deg[d.x], 1); }
        if (d.y >= 0 && d.y < NMAX) { atomicAdd(&g_deg[d.y], 1); }
        if (d.z >= 0 && d.z < NMAX) { atomicAdd(&g_deg[d.z], 1); }
        if (d.w >= 0 && d.w < NMAX) { atomicAdd(&g_deg[d.w], 1); }
    } else {
        int lim = (i4 + 4 < e) ? i4 + 4 : e;
        for (int i = i4; i < lim; i++) {
            int d = edge_at(ei, (long)e + i);
            if (d >= 0 && d < NMAX) { atomicAdd(&g_deg[d], 1); }
        }
    }
}

// ---------------- 3-phase parallel scan ----------------
__global__ void k_scan1(int n) {
    __shared__ int wsum[8];
    int blk = blockIdx.x;
    int tid = threadIdx.x;
    int i = blk * SCAN_BLK + tid;
    int lane = tid & 31;
    int wid = tid >> 5;
    int v = (i < n) ? g_deg[i] : 0;
    if (i < n) {
        g_dinv[i] = rsqrtf((float)(v + 1));
    }
    int incl = v;
    #pragma unroll
    for (int off = 1; off < 32; off <<= 1) {
        int t = __shfl_up_sync(0xffffffffu, incl, off);
        if (lane >= off) { incl += t; }
    }
    if (lane == 31) { wsum[wid] = incl; }
    __syncthreads();
    if (wid == 0 && lane < 8) {
        int ws = wsum[lane];
        int wincl = ws;
        #pragma unroll
        for (int off = 1; off < 8; off <<= 1) {
            int t = __shfl_up_sync(0xffu, wincl, off);
            if (lane >= off) { wincl += t; }
        }
        wsum[lane] = wincl - ws;
        if (lane == 7) { g_bsum[blk] = wincl; }
    }
    __syncthreads();
    if (i < n) {
        g_rowptr[i] = wsum[wid] + incl - v;
    }
}

__global__ void k_scan2(int nblk) {
    __shared__ int wsum[8];
    int tid = threadIdx.x;
    int lane = tid & 31;
    int wid = tid >> 5;
    int v = (tid < nblk) ? g_bsum[tid] : 0;
    int incl = v;
    #pragma unroll
    for (int off = 1; off < 32; off <<= 1) {
        int t = __shfl_up_sync(0xffffffffu, incl, off);
        if (lane >= off) { incl += t; }
    }
    if (lane == 31) { wsum[wid] = incl; }
    __syncthreads();
    if (wid == 0 && lane < 8) {
        int ws = wsum[lane];
        int wincl = ws;
        #pragma unroll
        for (int off = 1; off < 8; off <<= 1) {
            int t = __shfl_up_sync(0xffu, wincl, off);
            if (lane >= off) { wincl += t; }
        }
        wsum[lane] = wincl - ws;
    }
    __syncthreads();
    if (tid < nblk) {
        g_boff[tid] = wsum[wid] + incl - v;
    }
}

__global__ void k_scan3(int n, int e_total) {
    int i = blockIdx.x * blockDim.x + threadIdx.x;
    if (i < n) {
        int r = g_rowptr[i] + g_boff[blockIdx.x];
        g_rowptr[i] = r;
        g_cursor[i] = r;
    }
    if (i == 0) {
        g_rowptr[n] = e_total;
    }
}

// ---------------- CSR fill ----------------
__global__ void k_fill(const void* __restrict__ ei, int e) {
    int i4 = (blockIdx.x * blockDim.x + threadIdx.x) * 4;
    if (i4 >= e) {
        return;
    }
    if (!g_is64 && (e & 3) == 0) {
        const int4* ps = (const int4*)(const int*)ei;
        const int4* pd = (const int4*)((const int*)ei + e);
        int4 s = ps[i4 >> 2];
        int4 d = pd[i4 >> 2];
        int sa[4];
        int da[4];
        sa[0] = s.x; sa[1] = s.y; sa[2] = s.z; sa[3] = s.w;
        da[0] = d.x; da[1] = d.y; da[2] = d.z; da[3] = d.w;
        #pragma unroll
        for (int j = 0; j < 4; j++) {
            int ss = sa[j];
            int dd = da[j];
            if (ss >= 0 && ss < NMAX && dd >= 0 && dd < NMAX) {
                int pos = atomicAdd(&g_cursor[dd], 1);
                if (pos >= 0 && pos < EMAX) {
                    g_col[pos] = ss;
                    g_w[pos] = g_dinv[ss];
                }
            }
        }
    } else {
        int lim = (i4 + 4 < e) ? i4 + 4 : e;
        for (int i = i4; i < lim; i++) {
            int s = edge_at(ei, i);
            int d = edge_at(ei, (long)e + i);
            if (s >= 0 && s < NMAX && d >= 0 && d < NMAX) {
                int pos = atomicAdd(&g_cursor[d], 1);
                if (pos >= 0 && pos < EMAX) {
                    g_col[pos] = s;
                    g_w[pos] = g_dinv[s];
                }
            }
        }
    }
}

// ---------------- f32 -> bf16 hi/lo split ----------------
__global__ void k_cvt(const float4* __restrict__ src,
                      __nv_bfloat162* __restrict__ hi,
                      __nv_bfloat162* __restrict__ lo, int n4) {
    int i = blockIdx.x * blockDim.x + threadIdx.x;
    if (i >= n4) {
        return;
    }
    float4 v = src[i];
    __nv_bfloat16 h0 = __float2bfloat16(v.x);
    __nv_bfloat16 h1 = __float2bfloat16(v.y);
    __nv_bfloat16 h2 = __float2bfloat16(v.z);
    __nv_bfloat16 h3 = __float2bfloat16(v.w);
    __nv_bfloat16 l0 = __float2bfloat16(v.x - __bfloat162float(h0));
    __nv_bfloat16 l1 = __float2bfloat16(v.y - __bfloat162float(h1));
    __nv_bfloat16 l2 = __float2bfloat16(v.z - __bfloat162float(h2));
    __nv_bfloat16 l3 = __float2bfloat16(v.w - __bfloat162float(h3));
    hi[2 * i]     = __halves2bfloat162(h0, h1);
    hi[2 * i + 1] = __halves2bfloat162(h2, h3);
    lo[2 * i]     = __halves2bfloat162(l0, l1);
    lo[2 * i + 1] = __halves2bfloat162(l2, l3);
}

__global__ void k_cvt_w(const float* __restrict__ W1, const float* __restrict__ W2) {
    int i = blockIdx.x * blockDim.x + threadIdx.x;
    if (i < 128 * 128) {
        float v = W1[i];
        __nv_bfloat16 h = __float2bfloat16(v);
        g_W1h[i] = h;
        g_W1l[i] = __float2bfloat16(v - __bfloat162float(h));
    } else if (i < 128 * 128 + 128 * 64) {
        int j = i - 128 * 128;
        float v = W2[j];
        __nv_bfloat16 h = __float2bfloat16(v);
        g_W2h[j] = h;
        g_W2l[j] = __float2bfloat16(v - __bfloat162float(h));
    }
}

// ---------------- smem-staged wmma bf16x3 GEMM ----------------
// C[.,ND] = Ah@Bh + Ah@Bl + Al@Bh (fp32 acc). CTA tile 128x64, BK=32.
// 8 warps (4m x 2n), warp 32x32 via 2x2 m16n16k16 fragments.
// Grid: (rows/128, ND/64). Buffers padded to NPAD rows -> no bounds checks.
template<int ND>
__global__ void __launch_bounds__(256) k_gemm_wmma(
    const __nv_bfloat16* __restrict__ Ahp, const __nv_bfloat16* __restrict__ Alp,
    const __nv_bfloat16* __restrict__ Bhp, const __nv_bfloat16* __restrict__ Blp,
    float* __restrict__ C)
{
    using namespace nvcuda;
    const int KD = 128;
    const int AS = 40;   // smem A row stride (bf16 elems)
    const int BS = 72;   // smem B row stride

    __shared__ __align__(16) __nv_bfloat16 sAh[128 * AS];
    __shared__ __align__(16) __nv_bfloat16 sAl[128 * AS];
    __shared__ __align__(16) __nv_bfloat16 sBh[32 * BS];
    __shared__ __align__(16) __nv_bfloat16 sBl[32 * BS];

    int tid = threadIdx.x;
    int wid = tid >> 5;
    int wm = (wid & 3) * 32;           // warp m offset within CTA tile
    int wnl = (wid >> 2) * 32;         // warp n offset within 64-col block
    int bm = blockIdx.x * 128;
    int bn = blockIdx.y * 64;

    wmma::fragment<wmma::accumulator, 16, 16, 16, float> c[2][2];
    #pragma unroll
    for (int i = 0; i < 2; i++) {
        #pragma unroll
        for (int j = 0; j < 2; j++) {
            wmma::fill_fragment(c[i][j], 0.0f);
        }
    }

    for (int k0 = 0; k0 < KD; k0 += 32) {
        // A tiles: 128 rows x 32 cols = 512 uint4 chunks each (hi, lo)
        #pragma unroll
        for (int it = 0; it < 2; it++) {
            int f = tid + it * 256;
            int row = f >> 2;
            int cc = f & 3;
            long gidx = (long)(bm + row) * KD + k0 + 8 * cc;
            *(uint4*)&sAh[row * AS + 8 * cc] = *(const uint4*)&Ahp[gidx];
            *(uint4*)&sAl[row * AS + 8 * cc] = *(const uint4*)&Alp[gidx];
        }
        // B tiles: 32 rows x 64 cols = 256 uint4 chunks each
        {
            int row = tid >> 3;
            int cc = tid & 7;
            long gidx = (long)(k0 + row) * ND + bn + 8 * cc;
            *(uint4*)&sBh[row * BS + 8 * cc] = *(const uint4*)&Bhp[gidx];
            *(uint4*)&sBl[row * BS + 8 * cc] = *(const uint4*)&Blp[gidx];
        }
        __syncthreads();

        #pragma unroll
        for (int ks = 0; ks < 32; ks += 16) {
            wmma::fragment<wmma::matrix_a, 16, 16, 16, __nv_bfloat16, wmma::row_major> ah[2];
            wmma::fragment<wmma::matrix_a, 16, 16, 16, __nv_bfloat16, wmma::row_major> al[2];
            wmma::fragment<wmma::matrix_b, 16, 16, 16, __nv_bfloat16, wmma::row_major> bh[2];
            wmma::fragment<wmma::matrix_b, 16, 16, 16, __nv_bfloat16, wmma::row_major> bl[2];
            #pragma unroll
            for (int i = 0; i < 2; i++) {
                wmma::load_matrix_sync(ah[i], &sAh[(wm + 16 * i) * AS + ks], AS);
                wmma::load_matrix_sync(al[i], &sAl[(wm + 16 * i) * AS + ks], AS);
            }
            #pragma unroll
            for (int j = 0; j < 2; j++) {
                wmma::load_matrix_sync(bh[j], &sBh[ks * BS + wnl + 16 * j], BS);
                wmma::load_matrix_sync(bl[j], &sBl[ks * BS + wnl + 16 * j], BS);
            }
            #pragma unroll
            for (int i = 0; i < 2; i++) {
                #pragma unroll
                for (int j = 0; j < 2; j++) {
                    wmma::mma_sync(c[i][j], ah[i], bh[j], c[i][j]);
                    wmma::mma_sync(c[i][j], ah[i], bl[j], c[i][j]);
                    wmma::mma_sync(c[i][j], al[i], bh[j], c[i][j]);
                }
            }
        }
        __syncthreads();
    }

    #pragma unroll
    for (int i = 0; i < 2; i++) {
        #pragma unroll
        for (int j = 0; j < 2; j++) {
            wmma::store_matrix_sync(C + (long)(bm + wm + 16 * i) * ND + bn + wnl + 16 * j,
                                    c[i][j], ND, wmma::mem_row_major);
        }
    }
}

// ---------------- layer-1 aggregation (F=128) -> writes h1 as bf16 hi/lo ----------------
// out = tanh(dinv_d * (sum w_p*H[s] + dinv_d*H[d]) + b)
__global__ void __launch_bounds__(256) k_agg128(const float* __restrict__ h,
                                                const float* __restrict__ bias,
                                                int n) {
    int node = blockIdx.x * 8 + (threadIdx.x >> 5);
    if (node >= n) {
        return;
    }
    int lane = threadIdx.x & 31;
    const float4* hv = (const float4*)h;
    float di = g_dinv[node];
    float4 a = __ldg(&hv[(long)node * 32 + lane]);
    float4 acc;
    acc.x = di * a.x;
    acc.y = di * a.y;
    acc.z = di * a.z;
    acc.w = di * a.w;
    int beg = g_rowptr[node];
    int end = g_rowptr[node + 1];
    #pragma unroll 4
    for (int p = beg; p < end; p++) {
        int s = g_col[p];
        float ws = g_w[p];
        float4 v = __ldg(&hv[(long)s * 32 + lane]);
        acc.x += ws * v.x;
        acc.y += ws * v.y;
        acc.z += ws * v.z;
        acc.w += ws * v.w;
    }
    float4 b = __ldg(&((const float4*)bias)[lane]);
    float rx = tanhf(di * acc.x + b.x);
    float ry = tanhf(di * acc.y + b.y);
    float rz = tanhf(di * acc.z + b.z);
    float rw = tanhf(di * acc.w + b.w);
    __nv_bfloat16 h0 = __float2bfloat16(rx);
    __nv_bfloat16 h1 = __float2bfloat16(ry);
    __nv_bfloat16 h2 = __float2bfloat16(rz);
    __nv_bfloat16 h3 = __float2bfloat16(rw);
    __nv_bfloat16 l0 = __float2bfloat16(rx - __bfloat162float(h0));
    __nv_bfloat16 l1 = __float2bfloat16(ry - __bfloat162float(h1));
    __nv_bfloat16 l2 = __float2bfloat16(rz - __bfloat162float(h2));
    __nv_bfloat16 l3 = __float2bfloat16(rw - __bfloat162float(h3));
    __nv_bfloat162* hh = (__nv_bfloat162*)g_h1h;
    __nv_bfloat162* hl = (__nv_bfloat162*)g_h1l;
    long idx = (long)node * 64 + 2 * lane;
    hh[idx]     = __halves2bfloat162(h0, h1);
    hh[idx + 1] = __halves2bfloat162(h2, h3);
    hl[idx]     = __halves2bfloat162(l0, l1);
    hl[idx + 1] = __halves2bfloat162(l2, l3);
}

// ---------------- fused agg(F=64, weighted) + MLP head ----------------
__global__ void __launch_bounds__(256) k_agg64_mlp(const float* __restrict__ h,
                                                   const float* __restrict__ b2,
                                                   const float* __restrict__ Wf1,
                                                   const float* __restrict__ bf1,
                                                   const float* __restrict__ Wf2,
                                                   const float* __restrict__ bf2,
                                                   float* __restrict__ out, int n) {
    __shared__ float sW[64 * 32];
    __shared__ float sb1[32];
    __shared__ float sW2[32];
    __shared__ float sb2;
    __shared__ float stage[8][64];
    for (int i = threadIdx.x; i < 64 * 32; i += blockDim.x) {
        sW[i] = Wf1[i];
    }
    if (threadIdx.x < 32) {
        sb1[threadIdx.x] = bf1[threadIdx.x];
        sW2[threadIdx.x] = Wf2[threadIdx.x];
    }
    if (threadIdx.x == 0) {
        sb2 = bf2[0];
    }
    __syncthreads();

    int w = threadIdx.x >> 5;
    int node = blockIdx.x * 8 + w;
    if (node >= n) {
        return;
    }
    int lane = threadIdx.x & 31;

    const float2* hv = (const float2*)h;
    float di = g_dinv[node];
    float2 a = __ldg(&hv[(long)node * 32 + lane]);
    float2 acc;
    acc.x = di * a.x;
    acc.y = di * a.y;
    int beg = g_rowptr[node];
    int end = g_rowptr[node + 1];
    #pragma unroll 4
    for (int p = beg; p < end; p++) {
        int s = g_col[p];
        float ws = g_w[p];
        float2 v = __ldg(&hv[(long)s * 32 + lane]);
        acc.x += ws * v.x;
        acc.y += ws * v.y;
    }
    float2 bb = __ldg(&((const float2*)b2)[lane]);
    stage[w][2 * lane]     = tanhf(di * acc.x + bb.x);
    stage[w][2 * lane + 1] = tanhf(di * acc.y + bb.y);
    __syncwarp();

    float a1 = sb1[lane];
    #pragma unroll
    for (int j = 0; j < 64; j++) {
        a1 += stage[w][j] * sW[j * 32 + lane];
    }
    float t = tanhf(a1);
    float y = t * sW2[lane];
    #pragma unroll
    for (int off = 16; off; off >>= 1) {
        y += __shfl_down_sync(0xffffffffu, y, off);
    }
    if (lane == 0) {
        out[node] = y + sb2;
    }
}

// ---------------- launch ----------------
extern "C" void kernel_launch(void* const* d_in, const int* in_sizes, int n_in,
                              void* d_out, int out_size) {
    const float* x   = (const float*)d_in[0];
    const void*  ei  = d_in[1];
    const float* W1  = (const float*)d_in[2];
    const float* b1  = (const float*)d_in[3];
    const float* W2  = (const float*)d_in[4];
    const float* b2  = (const float*)d_in[5];
    const float* Wf1 = (const float*)d_in[6];
    const float* bf1 = (const float*)d_in[7];
    const float* Wf2 = (const float*)d_in[8];
    const float* bf2 = (const float*)d_in[9];
    float* out = (float*)d_out;

    int n = in_sizes[0] / 128;   // 50000
    int e = in_sizes[1] / 2;     // 800000

    float* bufA = 0;
    float* bufB = 0;
    int* degp = 0;
    void* xh = 0;
    void* xl = 0;
    void* h1h = 0;
    void* h1l = 0;
    void* w1h = 0;
    void* w1l = 0;
    void* w2h = 0;
    void* w2l = 0;
    cudaGetSymbolAddress((void**)&bufA, g_bufA);
    cudaGetSymbolAddress((void**)&bufB, g_bufB);
    cudaGetSymbolAddress((void**)&degp, g_deg);
    cudaGetSymbolAddress(&xh, g_xh);
    cudaGetSymbolAddress(&xl, g_xl);
    cudaGetSymbolAddress(&h1h, g_h1h);
    cudaGetSymbolAddress(&h1l, g_h1l);
    cudaGetSymbolAddress(&w1h, g_W1h);
    cudaGetSymbolAddress(&w1l, g_W1l);
    cudaGetSymbolAddress(&w2h, g_W2h);
    cudaGetSymbolAddress(&w2l, g_W2l);

    static cudaStream_t sB = 0;
    static cudaEvent_t evFork = 0;
    static cudaEvent_t evJoin = 0;
    if (sB == 0) {
        cudaStreamCreateWithFlags(&sB, cudaStreamNonBlocking);
        cudaEventCreateWithFlags(&evFork, cudaEventDisableTiming);
        cudaEventCreateWithFlags(&evJoin, cudaEventDisableTiming);
    }

    int ge4 = (e + 1023) / 1024;
    int gw  = (n + 7) / 8;
    int gm  = (n + 127) / 128;   // 391, NPAD covers gm*128 rows

    // Fork: CSR build on side stream (fully independent of GEMM path)
    cudaEventRecord(evFork, 0);
    cudaStreamWaitEvent(sB, evFork, 0);

    k_detect<<<1, 1024, 0, sB>>>(ei, e);
    cudaMemsetAsync(degp, 0, (size_t)n * sizeof(int), sB);
    k_count<<<ge4, 256, 0, sB>>>(ei, e);
    k_scan1<<<SCAN_GRID, SCAN_BLK, 0, sB>>>(n);
    k_scan2<<<1, 256, 0, sB>>>(SCAN_GRID);
    k_scan3<<<SCAN_GRID, SCAN_BLK, 0, sB>>>(n, e);
    k_fill<<<ge4, 256, 0, sB>>>(ei, e);
    cudaEventRecord(evJoin, sB);

    // Main stream: conversions + GEMM1 (graph-independent)
    int n4 = n * 128 / 4;
    k_cvt<<<(n4 + 255) / 256, 256>>>((const float4*)x, (__nv_bfloat162*)xh,
                                     (__nv_bfloat162*)xl, n4);
    k_cvt_w<<<(128 * 128 + 128 * 64 + 255) / 256, 256>>>(W1, W2);
    {
        dim3 grid(gm, 2);
        k_gemm_wmma<128><<<grid, 256>>>((const __nv_bfloat16*)xh, (const __nv_bfloat16*)xl,
                                        (const __nv_bfloat16*)w1h, (const __nv_bfloat16*)w1l,
                                        bufA);
    }

    // Join: aggregation needs CSR + dinv + w
    cudaStreamWaitEvent(0, evJoin, 0);
    k_agg128<<<gw, 256>>>(bufA, b1, n);

    // Layer 2: wmma bf16x3 GEMM + fused weighted agg64 + MLP head
    {
        dim3 grid(gm, 1);
        k_gemm_wmma<64><<<grid, 256>>>((const __nv_bfloat16*)h1h, (const __nv_bfloat16*)h1l,
                                       (const __nv_bfloat16*)w2h, (const __nv_bfloat16*)w2l,
                                       bufB);
    }
    k_agg64_mlp<<<gw, 256>>>(bufB, b2, Wf1, bf1, Wf2, bf2, out, n);
}

// round 15
// speedup vs baseline: 1.2589x; 1.0334x over previous
#include <cuda_runtime.h>
#include <cuda_bf16.h>
#include <mma.h>
#include <math.h>

// Problem-fixed capacities
#define NMAX 50000
#define NPAD 50048
#define EMAX 800000
#define SCAN_BLK 256
#define SCAN_GRID ((NMAX + SCAN_BLK - 1) / SCAN_BLK)   // 196

// ---------------- scratch (no allocation allowed) ----------------
__device__ int   g_is64;
__device__ int   g_deg[NMAX];
__device__ int   g_cursor[NMAX];
__device__ float g_dinv[NMAX];
__device__ int   g_rowptr[NMAX + 1];
__device__ int   g_col[EMAX];
__device__ float g_w[EMAX];
__device__ int   g_bsum[SCAN_GRID];
__device__ int   g_boff[SCAN_GRID];
__device__ __align__(256) float g_bufA[NPAD * 128];   // GEMM1 out (f32)
__device__ __align__(256) float g_h1[NPAD * 128];     // agg128 out (f32; pad rows stay 0)
__device__ __align__(256) float g_bufB[NPAD * 64];    // GEMM2 out (f32)

// Edge index accessor: handles int32 (JAX x64-disabled) and int64 layouts.
__device__ __forceinline__ int edge_at(const void* ei, long idx) {
    if (g_is64) {
        return (int)((const long long*)ei)[idx];
    }
    return ((const int*)ei)[idx];
}

// ---------------- dtype detection ----------------
__global__ void k_detect(const void* ei, int e) {
    const long long* p = (const long long*)ei;
    int m = e < 2048 ? e : 2048;
    int ok = 1;
    for (int i = threadIdx.x; i < m; i += blockDim.x) {
        long long v = p[i];
        if (v < 0 || v >= NMAX) {
            ok = 0;
        }
    }
    int all = __syncthreads_and(ok);
    if (threadIdx.x == 0) {
        g_is64 = all;
    }
}

// ---------------- degree count ----------------
__global__ void k_count(const void* __restrict__ ei, int e) {
    int i4 = (blockIdx.x * blockDim.x + threadIdx.x) * 4;
    if (i4 >= e) {
        return;
    }
    if (!g_is64 && (e & 3) == 0) {
        const int4* p = (const int4*)((const int*)ei + e);
        int4 d = p[i4 >> 2];
        if (d.x >= 0 && d.x < NMAX) { atomicAdd(&g_deg[d.x], 1); }
        if (d.y >= 0 && d.y < NMAX) { atomicAdd(&g_deg[d.y], 1); }
        if (d.z >= 0 && d.z < NMAX) { atomicAdd(&g_deg[d.z], 1); }
        if (d.w >= 0 && d.w < NMAX) { atomicAdd(&g_deg[d.w], 1); }
    } else {
        int lim = (i4 + 4 < e) ? i4 + 4 : e;
        for (int i = i4; i < lim; i++) {
            int d = edge_at(ei, (long)e + i);
            if (d >= 0 && d < NMAX) { atomicAdd(&g_deg[d], 1); }
        }
    }
}

// ---------------- 3-phase parallel scan ----------------
__global__ void k_scan1(int n) {
    __shared__ int wsum[8];
    int blk = blockIdx.x;
    int tid = threadIdx.x;
    int i = blk * SCAN_BLK + tid;
    int lane = tid & 31;
    int wid = tid >> 5;
    int v = (i < n) ? g_deg[i] : 0;
    if (i < n) {
        g_dinv[i] = rsqrtf((float)(v + 1));
    }
    int incl = v;
    #pragma unroll
    for (int off = 1; off < 32; off <<= 1) {
        int t = __shfl_up_sync(0xffffffffu, incl, off);
        if (lane >= off) { incl += t; }
    }
    if (lane == 31) { wsum[wid] = incl; }
    __syncthreads();
    if (wid == 0 && lane < 8) {
        int ws = wsum[lane];
        int wincl = ws;
        #pragma unroll
        for (int off = 1; off < 8; off <<= 1) {
            int t = __shfl_up_sync(0xffu, wincl, off);
            if (lane >= off) { wincl += t; }
        }
        wsum[lane] = wincl - ws;
        if (lane == 7) { g_bsum[blk] = wincl; }
    }
    __syncthreads();
    if (i < n) {
        g_rowptr[i] = wsum[wid] + incl - v;
    }
}

__global__ void k_scan2(int nblk) {
    __shared__ int wsum[8];
    int tid = threadIdx.x;
    int lane = tid & 31;
    int wid = tid >> 5;
    int v = (tid < nblk) ? g_bsum[tid] : 0;
    int incl = v;
    #pragma unroll
    for (int off = 1; off < 32; off <<= 1) {
        int t = __shfl_up_sync(0xffffffffu, incl, off);
        if (lane >= off) { incl += t; }
    }
    if (lane == 31) { wsum[wid] = incl; }
    __syncthreads();
    if (wid == 0 && lane < 8) {
        int ws = wsum[lane];
        int wincl = ws;
        #pragma unroll
        for (int off = 1; off < 8; off <<= 1) {
            int t = __shfl_up_sync(0xffu, wincl, off);
            if (lane >= off) { wincl += t; }
        }
        wsum[lane] = wincl - ws;
    }
    __syncthreads();
    if (tid < nblk) {
        g_boff[tid] = wsum[wid] + incl - v;
    }
}

__global__ void k_scan3(int n, int e_total) {
    int i = blockIdx.x * blockDim.x + threadIdx.x;
    if (i < n) {
        int r = g_rowptr[i] + g_boff[blockIdx.x];
        g_rowptr[i] = r;
        g_cursor[i] = r;
    }
    if (i == 0) {
        g_rowptr[n] = e_total;
    }
}

// ---------------- CSR fill ----------------
__global__ void k_fill(const void* __restrict__ ei, int e) {
    int i4 = (blockIdx.x * blockDim.x + threadIdx.x) * 4;
    if (i4 >= e) {
        return;
    }
    if (!g_is64 && (e & 3) == 0) {
        const int4* ps = (const int4*)(const int*)ei;
        const int4* pd = (const int4*)((const int*)ei + e);
        int4 s = ps[i4 >> 2];
        int4 d = pd[i4 >> 2];
        int sa[4];
        int da[4];
        sa[0] = s.x; sa[1] = s.y; sa[2] = s.z; sa[3] = s.w;
        da[0] = d.x; da[1] = d.y; da[2] = d.z; da[3] = d.w;
        #pragma unroll
        for (int j = 0; j < 4; j++) {
            int ss = sa[j];
            int dd = da[j];
            if (ss >= 0 && ss < NMAX && dd >= 0 && dd < NMAX) {
                int pos = atomicAdd(&g_cursor[dd], 1);
                if (pos >= 0 && pos < EMAX) {
                    g_col[pos] = ss;
                    g_w[pos] = g_dinv[ss];
                }
            }
        }
    } else {
        int lim = (i4 + 4 < e) ? i4 + 4 : e;
        for (int i = i4; i < lim; i++) {
            int s = edge_at(ei, i);
            int d = edge_at(ei, (long)e + i);
            if (s >= 0 && s < NMAX && d >= 0 && d < NMAX) {
                int pos = atomicAdd(&g_cursor[d], 1);
                if (pos >= 0 && pos < EMAX) {
                    g_col[pos] = s;
                    g_w[pos] = g_dinv[s];
                }
            }
        }
    }
}

// ---------------- smem-staged wmma bf16x3 GEMM, f32 inputs ----------------
// C[.,ND] = Ah@Bh + Ah@Bl + Al@Bh (fp32 acc) where (Ah,Al),(Bh,Bl) are hi/lo
// bf16 splits computed in the tile loaders. CTA tile 128x64, BK=32, 8 warps.
// Grid: (rows/128, ND/64). C padded to NPAD rows. A rows guarded against M.
template<int ND>
__global__ void __launch_bounds__(256) k_gemm_f32(
    const float* __restrict__ A, const float* __restrict__ B,
    float* __restrict__ C, int M)
{
    using namespace nvcuda;
    const int KD = 128;
    const int AS = 40;   // smem A row stride (bf16 elems)
    const int BS = 72;   // smem B row stride

    __shared__ __align__(16) __nv_bfloat16 sAh[128 * AS];
    __shared__ __align__(16) __nv_bfloat16 sAl[128 * AS];
    __shared__ __align__(16) __nv_bfloat16 sBh[32 * BS];
    __shared__ __align__(16) __nv_bfloat16 sBl[32 * BS];

    int tid = threadIdx.x;
    int wid = tid >> 5;
    int wm = (wid & 3) * 32;           // warp m offset within CTA tile
    int wnl = (wid >> 2) * 32;         // warp n offset within 64-col block
    int bm = blockIdx.x * 128;
    int bn = blockIdx.y * 64;

    wmma::fragment<wmma::accumulator, 16, 16, 16, float> c[2][2];
    #pragma unroll
    for (int i = 0; i < 2; i++) {
        #pragma unroll
        for (int j = 0; j < 2; j++) {
            wmma::fill_fragment(c[i][j], 0.0f);
        }
    }

    for (int k0 = 0; k0 < KD; k0 += 32) {
        // A tile: 128 rows x 32 cols = 512 chunks of 8 elems; convert f32 -> hi/lo
        #pragma unroll
        for (int it = 0; it < 2; it++) {
            int f = tid + it * 256;
            int row = f >> 2;
            int cc = f & 3;
            int gm = bm + row;
            float4 v0 = make_float4(0.f, 0.f, 0.f, 0.f);
            float4 v1 = make_float4(0.f, 0.f, 0.f, 0.f);
            if (gm < M) {
                v0 = *(const float4*)&A[(long)gm * KD + k0 + 8 * cc];
                v1 = *(const float4*)&A[(long)gm * KD + k0 + 8 * cc + 4];
            }
            float vv[8];
            vv[0] = v0.x; vv[1] = v0.y; vv[2] = v0.z; vv[3] = v0.w;
            vv[4] = v1.x; vv[5] = v1.y; vv[6] = v1.z; vv[7] = v1.w;
            alignas(16) __nv_bfloat16 hh[8];
            alignas(16) __nv_bfloat16 ll[8];
            #pragma unroll
            for (int j = 0; j < 8; j++) {
                __nv_bfloat16 h = __float2bfloat16(vv[j]);
                hh[j] = h;
                ll[j] = __float2bfloat16(vv[j] - __bfloat162float(h));
            }
            *(uint4*)&sAh[row * AS + 8 * cc] = *(const uint4*)hh;
            *(uint4*)&sAl[row * AS + 8 * cc] = *(const uint4*)ll;
        }
        // B tile: 32 rows x 64 cols = 256 chunks of 8 elems
        {
            int row = tid >> 3;
            int cc = tid & 7;
            long gidx = (long)(k0 + row) * ND + bn + 8 * cc;
            float4 v0 = *(const float4*)&B[gidx];
            float4 v1 = *(const float4*)&B[gidx + 4];
            float vv[8];
            vv[0] = v0.x; vv[1] = v0.y; vv[2] = v0.z; vv[3] = v0.w;
            vv[4] = v1.x; vv[5] = v1.y; vv[6] = v1.z; vv[7] = v1.w;
            alignas(16) __nv_bfloat16 hh[8];
            alignas(16) __nv_bfloat16 ll[8];
            #pragma unroll
            for (int j = 0; j < 8; j++) {
                __nv_bfloat16 h = __float2bfloat16(vv[j]);
                hh[j] = h;
                ll[j] = __float2bfloat16(vv[j] - __bfloat162float(h));
            }
            *(uint4*)&sBh[row * BS + 8 * cc] = *(const uint4*)hh;
            *(uint4*)&sBl[row * BS + 8 * cc] = *(const uint4*)ll;
        }
        __syncthreads();

        #pragma unroll
        for (int ks = 0; ks < 32; ks += 16) {
            wmma::fragment<wmma::matrix_a, 16, 16, 16, __nv_bfloat16, wmma::row_major> ah[2];
            wmma::fragment<wmma::matrix_a, 16, 16, 16, __nv_bfloat16, wmma::row_major> al[2];
            wmma::fragment<wmma::matrix_b, 16, 16, 16, __nv_bfloat16, wmma::row_major> bh[2];
            wmma::fragment<wmma::matrix_b, 16, 16, 16, __nv_bfloat16, wmma::row_major> bl[2];
            #pragma unroll
            for (int i = 0; i < 2; i++) {
                wmma::load_matrix_sync(ah[i], &sAh[(wm + 16 * i) * AS + ks], AS);
                wmma::load_matrix_sync(al[i], &sAl[(wm + 16 * i) * AS + ks], AS);
            }
            #pragma unroll
            for (int j = 0; j < 2; j++) {
                wmma::load_matrix_sync(bh[j], &sBh[ks * BS + wnl + 16 * j], BS);
                wmma::load_matrix_sync(bl[j], &sBl[ks * BS + wnl + 16 * j], BS);
            }
            #pragma unroll
            for (int i = 0; i < 2; i++) {
                #pragma unroll
                for (int j = 0; j < 2; j++) {
                    wmma::mma_sync(c[i][j], ah[i], bh[j], c[i][j]);
                    wmma::mma_sync(c[i][j], ah[i], bl[j], c[i][j]);
                    wmma::mma_sync(c[i][j], al[i], bh[j], c[i][j]);
                }
            }
        }
        __syncthreads();
    }

    #pragma unroll
    for (int i = 0; i < 2; i++) {
        #pragma unroll
        for (int j = 0; j < 2; j++) {
            wmma::store_matrix_sync(C + (long)(bm + wm + 16 * i) * ND + bn + wnl + 16 * j,
                                    c[i][j], ND, wmma::mem_row_major);
        }
    }
}

// ---------------- layer-1 aggregation (F=128, weighted) -> f32 h1 ----------------
// out = tanh(dinv_d * (sum w_p*H[s] + dinv_d*H[d]) + b)
__global__ void __launch_bounds__(256) k_agg128(const float* __restrict__ h,
                                                const float* __restrict__ bias,
                                                float* __restrict__ out, int n) {
    int node = blockIdx.x * 8 + (threadIdx.x >> 5);
    if (node >= n) {
        return;
    }
    int lane = threadIdx.x & 31;
    const float4* hv = (const float4*)h;
    float di = g_dinv[node];
    float4 a = __ldg(&hv[(long)node * 32 + lane]);
    float4 acc;
    acc.x = di * a.x;
    acc.y = di * a.y;
    acc.z = di * a.z;
    acc.w = di * a.w;
    int beg = g_rowptr[node];
    int end = g_rowptr[node + 1];
    #pragma unroll 4
    for (int p = beg; p < end; p++) {
        int s = g_col[p];
        float ws = g_w[p];
        float4 v = __ldg(&hv[(long)s * 32 + lane]);
        acc.x += ws * v.x;
        acc.y += ws * v.y;
        acc.z += ws * v.z;
        acc.w += ws * v.w;
    }
    float4 b = __ldg(&((const float4*)bias)[lane]);
    float4 r;
    r.x = tanhf(di * acc.x + b.x);
    r.y = tanhf(di * acc.y + b.y);
    r.z = tanhf(di * acc.z + b.z);
    r.w = tanhf(di * acc.w + b.w);
    ((float4*)out)[(long)node * 32 + lane] = r;
}

// ---------------- fused agg(F=64, weighted) + MLP head ----------------
__global__ void __launch_bounds__(256) k_agg64_mlp(const float* __restrict__ h,
                                                   const float* __restrict__ b2,
                                                   const float* __restrict__ Wf1,
                                                   const float* __restrict__ bf1,
                                                   const float* __restrict__ Wf2,
                                                   const float* __restrict__ bf2,
                                                   float* __restrict__ out, int n) {
    __shared__ float sW[64 * 32];
    __shared__ float sb1[32];
    __shared__ float sW2[32];
    __shared__ float sb2;
    __shared__ float stage[8][64];
    for (int i = threadIdx.x; i < 64 * 32; i += blockDim.x) {
        sW[i] = Wf1[i];
    }
    if (threadIdx.x < 32) {
        sb1[threadIdx.x] = bf1[threadIdx.x];
        sW2[threadIdx.x] = Wf2[threadIdx.x];
    }
    if (threadIdx.x == 0) {
        sb2 = bf2[0];
    }
    __syncthreads();

    int w = threadIdx.x >> 5;
    int node = blockIdx.x * 8 + w;
    if (node >= n) {
        return;
    }
    int lane = threadIdx.x & 31;

    const float2* hv = (const float2*)h;
    float di = g_dinv[node];
    float2 a = __ldg(&hv[(long)node * 32 + lane]);
    float2 acc;
    acc.x = di * a.x;
    acc.y = di * a.y;
    int beg = g_rowptr[node];
    int end = g_rowptr[node + 1];
    #pragma unroll 4
    for (int p = beg; p < end; p++) {
        int s = g_col[p];
        float ws = g_w[p];
        float2 v = __ldg(&hv[(long)s * 32 + lane]);
        acc.x += ws * v.x;
        acc.y += ws * v.y;
    }
    float2 bb = __ldg(&((const float2*)b2)[lane]);
    stage[w][2 * lane]     = tanhf(di * acc.x + bb.x);
    stage[w][2 * lane + 1] = tanhf(di * acc.y + bb.y);
    __syncwarp();

    float a1 = sb1[lane];
    #pragma unroll
    for (int j = 0; j < 64; j++) {
        a1 += stage[w][j] * sW[j * 32 + lane];
    }
    float t = tanhf(a1);
    float y = t * sW2[lane];
    #pragma unroll
    for (int off = 16; off; off >>= 1) {
        y += __shfl_down_sync(0xffffffffu, y, off);
    }
    if (lane == 0) {
        out[node] = y + sb2;
    }
}

// ---------------- launch ----------------
extern "C" void kernel_launch(void* const* d_in, const int* in_sizes, int n_in,
                              void* d_out, int out_size) {
    const float* x   = (const float*)d_in[0];
    const void*  ei  = d_in[1];
    const float* W1  = (const float*)d_in[2];
    const float* b1  = (const float*)d_in[3];
    const float* W2  = (const float*)d_in[4];
    const float* b2  = (const float*)d_in[5];
    const float* Wf1 = (const float*)d_in[6];
    const float* bf1 = (const float*)d_in[7];
    const float* Wf2 = (const float*)d_in[8];
    const float* bf2 = (const float*)d_in[9];
    float* out = (float*)d_out;

    int n = in_sizes[0] / 128;   // 50000
    int e = in_sizes[1] / 2;     // 800000

    float* bufA = 0;
    float* h1 = 0;
    float* bufB = 0;
    int* degp = 0;
    cudaGetSymbolAddress((void**)&bufA, g_bufA);
    cudaGetSymbolAddress((void**)&h1, g_h1);
    cudaGetSymbolAddress((void**)&bufB, g_bufB);
    cudaGetSymbolAddress((void**)&degp, g_deg);

    static cudaStream_t sB = 0;
    static cudaEvent_t evFork = 0;
    static cudaEvent_t evJoin = 0;
    if (sB == 0) {
        cudaStreamCreateWithFlags(&sB, cudaStreamNonBlocking);
        cudaEventCreateWithFlags(&evFork, cudaEventDisableTiming);
        cudaEventCreateWithFlags(&evJoin, cudaEventDisableTiming);
    }

    int ge4 = (e + 1023) / 1024;
    int gw  = (n + 7) / 8;
    int gm  = (n + 127) / 128;   // 391, NPAD covers gm*128 rows

    // Fork: CSR build on side stream (fully independent of GEMM path)
    cudaEventRecord(evFork, 0);
    cudaStreamWaitEvent(sB, evFork, 0);

    k_detect<<<1, 1024, 0, sB>>>(ei, e);
    cudaMemsetAsync(degp, 0, (size_t)n * sizeof(int), sB);
    k_count<<<ge4, 256, 0, sB>>>(ei, e);
    k_scan1<<<SCAN_GRID, SCAN_BLK, 0, sB>>>(n);
    k_scan2<<<1, 256, 0, sB>>>(SCAN_GRID);
    k_scan3<<<SCAN_GRID, SCAN_BLK, 0, sB>>>(n, e);
    k_fill<<<ge4, 256, 0, sB>>>(ei, e);
    cudaEventRecord(evJoin, sB);

    // Main stream: GEMM1 (graph-independent, converts f32->bf16x2 in-loader)
    {
        dim3 grid(gm, 2);
        k_gemm_f32<128><<<grid, 256>>>(x, W1, bufA, n);
    }

    // Join: aggregation needs CSR + dinv + w
    cudaStreamWaitEvent(0, evJoin, 0);
    k_agg128<<<gw, 256>>>(bufA, b1, h1, n);

    // Layer 2: GEMM (h1 padded, pad rows are zero) + fused weighted agg64 + MLP head
    {
        dim3 grid(gm, 1);
        k_gemm_f32<64><<<grid, 256>>>(h1, W2, bufB, NPAD);
    }
    k_agg64_mlp<<<gw, 256>>>(bufB, b2, Wf1, bf1, Wf2, bf2, out, n);
}

// round 16
// speedup vs baseline: 1.2954x; 1.0290x over previous
#include <cuda_runtime.h>
#include <cuda_bf16.h>
#include <mma.h>
#include <math.h>

// Problem-fixed capacities
#define NMAX 50000
#define NPAD 50048
#define EMAX 800000
#define SCAN_BLK 256
#define SCAN_GRID ((NMAX + SCAN_BLK - 1) / SCAN_BLK)   // 196

// ---------------- scratch (no allocation allowed) ----------------
__device__ int   g_is64;
__device__ int   g_deg[NMAX];          // zero-initialized; self-cleaned by k_scan
__device__ int   g_cursor[NMAX];
__device__ float g_dinv[NMAX];
__device__ int   g_rowptr[NMAX + 1];
__device__ int   g_col[EMAX];
__device__ int            g_agg[SCAN_GRID];
__device__ volatile unsigned g_flag[SCAN_GRID];   // generation tags (monotonic)
__device__ unsigned g_tick;
__device__ __align__(256) float g_bufA[NPAD * 128];   // GEMM1 out (f32)
__device__ __align__(256) float g_h1[NPAD * 128];     // agg128 out (f32; pad rows stay 0)
__device__ __align__(256) float g_bufB[NPAD * 64];    // GEMM2 out (f32)

// Edge index accessor: handles int32 (JAX x64-disabled) and int64 layouts.
__device__ __forceinline__ int edge_at(const void* ei, long idx, int is64) {
    if (is64) {
        return (int)((const long long*)ei)[idx];
    }
    return ((const int*)ei)[idx];
}

// ---------------- degree count (detect folded in) ----------------
__global__ void k_count(const void* __restrict__ ei, int e) {
    __shared__ int s_is64;
    // per-block dtype detect on the first 2048 int64 slots (L2-resident)
    {
        const long long* p = (const long long*)ei;
        int m = e < 2048 ? e : 2048;
        int ok = 1;
        for (int i = threadIdx.x; i < m; i += blockDim.x) {
            long long v = p[i];
            if (v < 0 || v >= NMAX) {
                ok = 0;
            }
        }
        int all = __syncthreads_and(ok);
        if (threadIdx.x == 0) {
            s_is64 = all;
            g_is64 = all;   // benign same-value race; consumed by k_fill after stream ordering
        }
        __syncthreads();
    }
    int is64 = s_is64;

    int i4 = (blockIdx.x * blockDim.x + threadIdx.x) * 4;
    if (i4 >= e) {
        return;
    }
    if (!is64 && (e & 3) == 0) {
        const int4* p = (const int4*)((const int*)ei + e);
        int4 d = p[i4 >> 2];
        if (d.x >= 0 && d.x < NMAX) { atomicAdd(&g_deg[d.x], 1); }
        if (d.y >= 0 && d.y < NMAX) { atomicAdd(&g_deg[d.y], 1); }
        if (d.z >= 0 && d.z < NMAX) { atomicAdd(&g_deg[d.z], 1); }
        if (d.w >= 0 && d.w < NMAX) { atomicAdd(&g_deg[d.w], 1); }
    } else {
        int lim = (i4 + 4 < e) ? i4 + 4 : e;
        for (int i = i4; i < lim; i++) {
            int d = edge_at(ei, (long)e + i, is64);
            if (d >= 0 && d < NMAX) { atomicAdd(&g_deg[d], 1); }
        }
    }
}

// ---------------- single-kernel decoupled-lookback scan ----------------
// Computes exclusive prefix of g_deg into g_rowptr/g_cursor, dinv, and
// self-cleans g_deg for the next graph replay. Generation tags avoid flag
// resets: launch k uses gen=k+1 (g_tick/gridDim), flags are monotonic.
__global__ void k_scan(int n, int e_total) {
    __shared__ int wsum[8];
    __shared__ int s_total;
    __shared__ int s_prev;
    __shared__ unsigned s_gen;
    int blk = blockIdx.x;
    int tid = threadIdx.x;
    int lane = tid & 31;
    int wid = tid >> 5;
    int i = blk * SCAN_BLK + tid;

    if (tid == 0) {
        unsigned t = atomicAdd(&g_tick, 1u);
        s_gen = t / gridDim.x + 1u;
    }

    int v = (i < n) ? g_deg[i] : 0;
    if (i < n) {
        g_dinv[i] = rsqrtf((float)(v + 1));  // +1 self loop
        g_deg[i] = 0;                         // self-clean for next replay
    }

    // block-local scan
    int incl = v;
    #pragma unroll
    for (int off = 1; off < 32; off <<= 1) {
        int t = __shfl_up_sync(0xffffffffu, incl, off);
        if (lane >= off) { incl += t; }
    }
    if (lane == 31) { wsum[wid] = incl; }
    __syncthreads();
    if (wid == 0 && lane < 8) {
        int ws = wsum[lane];
        int wincl = ws;
        #pragma unroll
        for (int off = 1; off < 8; off <<= 1) {
            int t = __shfl_up_sync(0xffu, wincl, off);
            if (lane >= off) { wincl += t; }
        }
        wsum[lane] = wincl - ws;  // exclusive warp prefix
        if (lane == 7) {
            s_total = wincl;      // block total
            g_agg[blk] = wincl;   // publish
            __threadfence();
            g_flag[blk] = s_gen;
        }
    }
    __syncthreads();

    // lookback: warp 0 sums predecessors' aggregates (32-wide polling)
    if (wid == 0) {
        unsigned gen = s_gen;
        int sum = 0;
        for (int base = 0; base < blk; base += 32) {
            int j = base + lane;
            int a = 0;
            if (j < blk) {
                while (g_flag[j] != gen) { }
                __threadfence();
                a = g_agg[j];
            }
            #pragma unroll
            for (int off = 16; off; off >>= 1) {
                a += __shfl_down_sync(0xffffffffu, a, off);
            }
            if (lane == 0) { sum += a; }
        }
        if (lane == 0) { s_prev = sum; }
    }
    __syncthreads();

    int excl = s_prev + wsum[wid] + incl - v;
    if (i < n) {
        g_rowptr[i] = excl;
        g_cursor[i] = excl;
    }
    if (blk == 0 && tid == 0) {
        g_rowptr[n] = e_total;
    }
}

// ---------------- CSR fill (col only; weights read as dinv[src] in agg) ----------------
__global__ void k_fill(const void* __restrict__ ei, int e) {
    int is64 = g_is64;
    int i4 = (blockIdx.x * blockDim.x + threadIdx.x) * 4;
    if (i4 >= e) {
        return;
    }
    if (!is64 && (e & 3) == 0) {
        const int4* ps = (const int4*)(const int*)ei;
        const int4* pd = (const int4*)((const int*)ei + e);
        int4 s = ps[i4 >> 2];
        int4 d = pd[i4 >> 2];
        int sa[4];
        int da[4];
        sa[0] = s.x; sa[1] = s.y; sa[2] = s.z; sa[3] = s.w;
        da[0] = d.x; da[1] = d.y; da[2] = d.z; da[3] = d.w;
        #pragma unroll
        for (int j = 0; j < 4; j++) {
            int ss = sa[j];
            int dd = da[j];
            if (ss >= 0 && ss < NMAX && dd >= 0 && dd < NMAX) {
                int pos = atomicAdd(&g_cursor[dd], 1);
                if (pos >= 0 && pos < EMAX) {
                    g_col[pos] = ss;
                }
            }
        }
    } else {
        int lim = (i4 + 4 < e) ? i4 + 4 : e;
        for (int i = i4; i < lim; i++) {
            int s = edge_at(ei, i, is64);
            int d = edge_at(ei, (long)e + i, is64);
            if (s >= 0 && s < NMAX && d >= 0 && d < NMAX) {
                int pos = atomicAdd(&g_cursor[d], 1);
                if (pos >= 0 && pos < EMAX) {
                    g_col[pos] = s;
                }
            }
        }
    }
}

// ---------------- smem-staged wmma bf16x3 GEMM, f32 inputs ----------------
// C[.,ND] = Ah@Bh + Ah@Bl + Al@Bh (fp32 acc); hi/lo split in the tile loaders.
// CTA tile 128x64, BK=32, 8 warps. Grid: (rows/128, ND/64). C padded to NPAD rows.
template<int ND>
__global__ void __launch_bounds__(256) k_gemm_f32(
    const float* __restrict__ A, const float* __restrict__ B,
    float* __restrict__ C, int M)
{
    using namespace nvcuda;
    const int KD = 128;
    const int AS = 40;   // smem A row stride (bf16 elems)
    const int BS = 72;   // smem B row stride

    __shared__ __align__(16) __nv_bfloat16 sAh[128 * AS];
    __shared__ __align__(16) __nv_bfloat16 sAl[128 * AS];
    __shared__ __align__(16) __nv_bfloat16 sBh[32 * BS];
    __shared__ __align__(16) __nv_bfloat16 sBl[32 * BS];

    int tid = threadIdx.x;
    int wid = tid >> 5;
    int wm = (wid & 3) * 32;
    int wnl = (wid >> 2) * 32;
    int bm = blockIdx.x * 128;
    int bn = blockIdx.y * 64;

    wmma::fragment<wmma::accumulator, 16, 16, 16, float> c[2][2];
    #pragma unroll
    for (int i = 0; i < 2; i++) {
        #pragma unroll
        for (int j = 0; j < 2; j++) {
            wmma::fill_fragment(c[i][j], 0.0f);
        }
    }

    for (int k0 = 0; k0 < KD; k0 += 32) {
        #pragma unroll
        for (int it = 0; it < 2; it++) {
            int f = tid + it * 256;
            int row = f >> 2;
            int cc = f & 3;
            int gm = bm + row;
            float4 v0 = make_float4(0.f, 0.f, 0.f, 0.f);
            float4 v1 = make_float4(0.f, 0.f, 0.f, 0.f);
            if (gm < M) {
                v0 = *(const float4*)&A[(long)gm * KD + k0 + 8 * cc];
                v1 = *(const float4*)&A[(long)gm * KD + k0 + 8 * cc + 4];
            }
            float vv[8];
            vv[0] = v0.x; vv[1] = v0.y; vv[2] = v0.z; vv[3] = v0.w;
            vv[4] = v1.x; vv[5] = v1.y; vv[6] = v1.z; vv[7] = v1.w;
            alignas(16) __nv_bfloat16 hh[8];
            alignas(16) __nv_bfloat16 ll[8];
            #pragma unroll
            for (int j = 0; j < 8; j++) {
                __nv_bfloat16 h = __float2bfloat16(vv[j]);
                hh[j] = h;
                ll[j] = __float2bfloat16(vv[j] - __bfloat162float(h));
            }
            *(uint4*)&sAh[row * AS + 8 * cc] = *(const uint4*)hh;
            *(uint4*)&sAl[row * AS + 8 * cc] = *(const uint4*)ll;
        }
        {
            int row = tid >> 3;
            int cc = tid & 7;
            long gidx = (long)(k0 + row) * ND + bn + 8 * cc;
            float4 v0 = *(const float4*)&B[gidx];
            float4 v1 = *(const float4*)&B[gidx + 4];
            float vv[8];
            vv[0] = v0.x; vv[1] = v0.y; vv[2] = v0.z; vv[3] = v0.w;
            vv[4] = v1.x; vv[5] = v1.y; vv[6] = v1.z; vv[7] = v1.w;
            alignas(16) __nv_bfloat16 hh[8];
            alignas(16) __nv_bfloat16 ll[8];
            #pragma unroll
            for (int j = 0; j < 8; j++) {
                __nv_bfloat16 h = __float2bfloat16(vv[j]);
                hh[j] = h;
                ll[j] = __float2bfloat16(vv[j] - __bfloat162float(h));
            }
            *(uint4*)&sBh[row * BS + 8 * cc] = *(const uint4*)hh;
            *(uint4*)&sBl[row * BS + 8 * cc] = *(const uint4*)ll;
        }
        __syncthreads();

        #pragma unroll
        for (int ks = 0; ks < 32; ks += 16) {
            wmma::fragment<wmma::matrix_a, 16, 16, 16, __nv_bfloat16, wmma::row_major> ah[2];
            wmma::fragment<wmma::matrix_a, 16, 16, 16, __nv_bfloat16, wmma::row_major> al[2];
            wmma::fragment<wmma::matrix_b, 16, 16, 16, __nv_bfloat16, wmma::row_major> bh[2];
            wmma::fragment<wmma::matrix_b, 16, 16, 16, __nv_bfloat16, wmma::row_major> bl[2];
            #pragma unroll
            for (int i = 0; i < 2; i++) {
                wmma::load_matrix_sync(ah[i], &sAh[(wm + 16 * i) * AS + ks], AS);
                wmma::load_matrix_sync(al[i], &sAl[(wm + 16 * i) * AS + ks], AS);
            }
            #pragma unroll
            for (int j = 0; j < 2; j++) {
                wmma::load_matrix_sync(bh[j], &sBh[ks * BS + wnl + 16 * j], BS);
                wmma::load_matrix_sync(bl[j], &sBl[ks * BS + wnl + 16 * j], BS);
            }
            #pragma unroll
            for (int i = 0; i < 2; i++) {
                #pragma unroll
                for (int j = 0; j < 2; j++) {
                    wmma::mma_sync(c[i][j], ah[i], bh[j], c[i][j]);
                    wmma::mma_sync(c[i][j], ah[i], bl[j], c[i][j]);
                    wmma::mma_sync(c[i][j], al[i], bh[j], c[i][j]);
                }
            }
        }
        __syncthreads();
    }

    #pragma unroll
    for (int i = 0; i < 2; i++) {
        #pragma unroll
        for (int j = 0; j < 2; j++) {
            wmma::store_matrix_sync(C + (long)(bm + wm + 16 * i) * ND + bn + wnl + 16 * j,
                                    c[i][j], ND, wmma::mem_row_major);
        }
    }
}

// ---------------- layer-1 aggregation (F=128, dinv[src]-weighted) -> f32 h1 ----------------
// out = tanh(dinv_d * (sum dinv_s*H[s] + dinv_d*H[d]) + b)
__global__ void __launch_bounds__(256) k_agg128(const float* __restrict__ h,
                                                const float* __restrict__ bias,
                                                float* __restrict__ out, int n) {
    int node = blockIdx.x * 8 + (threadIdx.x >> 5);
    if (node >= n) {
        return;
    }
    int lane = threadIdx.x & 31;
    const float4* hv = (const float4*)h;
    float di = g_dinv[node];
    float4 a = __ldg(&hv[(long)node * 32 + lane]);
    float4 acc;
    acc.x = di * a.x;
    acc.y = di * a.y;
    acc.z = di * a.z;
    acc.w = di * a.w;
    int beg = g_rowptr[node];
    int end = g_rowptr[node + 1];
    #pragma unroll 4
    for (int p = beg; p < end; p++) {
        int s = g_col[p];
        float ws = g_dinv[s];
        float4 v = __ldg(&hv[(long)s * 32 + lane]);
        acc.x += ws * v.x;
        acc.y += ws * v.y;
        acc.z += ws * v.z;
        acc.w += ws * v.w;
    }
    float4 b = __ldg(&((const float4*)bias)[lane]);
    float4 r;
    r.x = tanhf(di * acc.x + b.x);
    r.y = tanhf(di * acc.y + b.y);
    r.z = tanhf(di * acc.z + b.z);
    r.w = tanhf(di * acc.w + b.w);
    ((float4*)out)[(long)node * 32 + lane] = r;
}

// ---------------- fused agg(F=64, dinv[src]-weighted) + MLP head ----------------
__global__ void __launch_bounds__(256) k_agg64_mlp(const float* __restrict__ h,
                                                   const float* __restrict__ b2,
                                                   const float* __restrict__ Wf1,
                                                   const float* __restrict__ bf1,
                                                   const float* __restrict__ Wf2,
                                                   const float* __restrict__ bf2,
                                                   float* __restrict__ out, int n) {
    __shared__ float sW[64 * 32];
    __shared__ float sb1[32];
    __shared__ float sW2[32];
    __shared__ float sb2;
    __shared__ float stage[8][64];
    for (int i = threadIdx.x; i < 64 * 32; i += blockDim.x) {
        sW[i] = Wf1[i];
    }
    if (threadIdx.x < 32) {
        sb1[threadIdx.x] = bf1[threadIdx.x];
        sW2[threadIdx.x] = Wf2[threadIdx.x];
    }
    if (threadIdx.x == 0) {
        sb2 = bf2[0];
    }
    __syncthreads();

    int w = threadIdx.x >> 5;
    int node = blockIdx.x * 8 + w;
    if (node >= n) {
        return;
    }
    int lane = threadIdx.x & 31;

    const float2* hv = (const float2*)h;
    float di = g_dinv[node];
    float2 a = __ldg(&hv[(long)node * 32 + lane]);
    float2 acc;
    acc.x = di * a.x;
    acc.y = di * a.y;
    int beg = g_rowptr[node];
    int end = g_rowptr[node + 1];
    #pragma unroll 4
    for (int p = beg; p < end; p++) {
        int s = g_col[p];
        float ws = g_dinv[s];
        float2 v = __ldg(&hv[(long)s * 32 + lane]);
        acc.x += ws * v.x;
        acc.y += ws * v.y;
    }
    float2 bb = __ldg(&((const float2*)b2)[lane]);
    stage[w][2 * lane]     = tanhf(di * acc.x + bb.x);
    stage[w][2 * lane + 1] = tanhf(di * acc.y + bb.y);
    __syncwarp();

    float a1 = sb1[lane];
    #pragma unroll
    for (int j = 0; j < 64; j++) {
        a1 += stage[w][j] * sW[j * 32 + lane];
    }
    float t = tanhf(a1);
    float y = t * sW2[lane];
    #pragma unroll
    for (int off = 16; off; off >>= 1) {
        y += __shfl_down_sync(0xffffffffu, y, off);
    }
    if (lane == 0) {
        out[node] = y + sb2;
    }
}

// ---------------- launch ----------------
extern "C" void kernel_launch(void* const* d_in, const int* in_sizes, int n_in,
                              void* d_out, int out_size) {
    const float* x   = (const float*)d_in[0];
    const void*  ei  = d_in[1];
    const float* W1  = (const float*)d_in[2];
    const float* b1  = (const float*)d_in[3];
    const float* W2  = (const float*)d_in[4];
    const float* b2  = (const float*)d_in[5];
    const float* Wf1 = (const float*)d_in[6];
    const float* bf1 = (const float*)d_in[7];
    const float* Wf2 = (const float*)d_in[8];
    const float* bf2 = (const float*)d_in[9];
    float* out = (float*)d_out;

    int n = in_sizes[0] / 128;   // 50000
    int e = in_sizes[1] / 2;     // 800000

    float* bufA = 0;
    float* h1 = 0;
    float* bufB = 0;
    cudaGetSymbolAddress((void**)&bufA, g_bufA);
    cudaGetSymbolAddress((void**)&h1, g_h1);
    cudaGetSymbolAddress((void**)&bufB, g_bufB);

    static cudaStream_t sB = 0;
    static cudaEvent_t evFork = 0;
    static cudaEvent_t evJoin = 0;
    if (sB == 0) {
        cudaStreamCreateWithFlags(&sB, cudaStreamNonBlocking);
        cudaEventCreateWithFlags(&evFork, cudaEventDisableTiming);
        cudaEventCreateWithFlags(&evJoin, cudaEventDisableTiming);
    }

    int ge4 = (e + 1023) / 1024;
    int gw  = (n + 7) / 8;
    int gm  = (n + 127) / 128;   // 391, NPAD covers gm*128 rows

    // Fork: 3-launch CSR build on side stream (independent of GEMM path)
    cudaEventRecord(evFork, 0);
    cudaStreamWaitEvent(sB, evFork, 0);

    k_count<<<ge4, 256, 0, sB>>>(ei, e);
    k_scan<<<SCAN_GRID, SCAN_BLK, 0, sB>>>(n, e);
    k_fill<<<ge4, 256, 0, sB>>>(ei, e);
    cudaEventRecord(evJoin, sB);

    // Main stream: GEMM1 (graph-independent, f32->bf16x2 split in-loader)
    {
        dim3 grid(gm, 2);
        k_gemm_f32<128><<<grid, 256>>>(x, W1, bufA, n);
    }

    // Join: aggregation needs CSR + dinv
    cudaStreamWaitEvent(0, evJoin, 0);
    k_agg128<<<gw, 256>>>(bufA, b1, h1, n);

    // Layer 2: GEMM (h1 padded, pad rows stay zero) + fused agg64 + MLP head
    {
        dim3 grid(gm, 1);
        k_gemm_f32<64><<<grid, 256>>>(h1, W2, bufB, NPAD);
    }
    k_agg64_mlp<<<gw, 256>>>(bufB, b2, Wf1, bf1, Wf2, bf2, out, n);
}